// round 2
// baseline (speedup 1.0000x reference)
#include <cuda_runtime.h>

#define EPSF 1e-8f

// Problem dims (compile-time)
#define KK 2048
#define MM 512
#define NN 64

// Output buffer layout (concatenated in reference return order)
#define OUT_OFF  0
#define HARD_OFF (KK * MM * NN)                 // 67,108,864
#define SOFT_OFF (HARD_OFF + MM * NN)           // +32,768
#define MASK_OFF (SOFT_OFF + KK * MM)           // +1,048,576

// ---------------------------------------------------------------------------
// K1: per-column 8th-largest threshold of w_b, then scores_hard [M, N]
// ---------------------------------------------------------------------------
__global__ void hard_kernel(const float* __restrict__ w_b, float* __restrict__ hard) {
    __shared__ float thr_s[NN];
    int tid = threadIdx.x;  // 512 threads
    if (tid < NN) {
        float t[8];
#pragma unroll
        for (int j = 0; j < 8; j++) t[j] = -1e30f;
        for (int m = 0; m < MM; m++) {
            float v = w_b[m * NN + tid];
            if (v > t[7]) {
                t[7] = v;
#pragma unroll
                for (int j = 7; j > 0; j--) {
                    if (t[j] > t[j - 1]) { float tmp = t[j]; t[j] = t[j - 1]; t[j - 1] = tmp; }
                }
            }
        }
        thr_s[tid] = t[7];
    }
    __syncthreads();
    for (int idx = tid; idx < MM * NN; idx += 512) {
        int n = idx & (NN - 1);
        float sh = w_b[idx] - thr_s[n] + EPSF;
        float c = fminf(fmaxf(sh, -1.0f), 1.0f);
        hard[idx] = (c + 1.0f) * 0.5f;
    }
}

// ---------------------------------------------------------------------------
// K2: C[2048,512] = A[2048,512] @ B[512,512]   (pre-softmax logits)
// 64x64 tile, BK=16, 256 threads, 4x4 microtile
// ---------------------------------------------------------------------------
__global__ __launch_bounds__(256) void gemm_kernel(const float* __restrict__ A,
                                                   const float* __restrict__ B,
                                                   float* __restrict__ C) {
    __shared__ float As[16][64];
    __shared__ float Bs[16][64];
    int tid  = threadIdx.x;
    int brow = blockIdx.x * 64;
    int bcol = blockIdx.y * 64;
    int tx = tid & 15, ty = tid >> 4;

    float acc[4][4] = {};

    int arow = tid >> 2;             // 0..63
    int ac4  = (tid & 3) * 4;        // 0,4,8,12
    int brl  = tid >> 4;             // 0..15
    int bc4  = (tid & 15) * 4;       // 0..60

    for (int k0 = 0; k0 < MM; k0 += 16) {
        float4 av = *(const float4*)&A[(brow + arow) * MM + k0 + ac4];
        As[ac4 + 0][arow] = av.x;
        As[ac4 + 1][arow] = av.y;
        As[ac4 + 2][arow] = av.z;
        As[ac4 + 3][arow] = av.w;
        float4 bv = *(const float4*)&B[(k0 + brl) * MM + bcol + bc4];
        *(float4*)&Bs[brl][bc4] = bv;
        __syncthreads();
#pragma unroll
        for (int k = 0; k < 16; k++) {
            float4 a = *(const float4*)&As[k][ty * 4];
            float4 b = *(const float4*)&Bs[k][tx * 4];
            float ar[4] = {a.x, a.y, a.z, a.w};
            float br[4] = {b.x, b.y, b.z, b.w};
#pragma unroll
            for (int i = 0; i < 4; i++)
#pragma unroll
                for (int j = 0; j < 4; j++)
                    acc[i][j] += ar[i] * br[j];
        }
        __syncthreads();
    }

#pragma unroll
    for (int i = 0; i < 4; i++) {
        float4 v = make_float4(acc[i][0], acc[i][1], acc[i][2], acc[i][3]);
        *(float4*)&C[(brow + ty * 4 + i) * MM + bcol + tx * 4] = v;
    }
}

// ---------------------------------------------------------------------------
// K3: row softmax over 512 in place, + EPS. One block (256 thr) per row.
// ---------------------------------------------------------------------------
__global__ __launch_bounds__(256) void softmax_kernel(float* __restrict__ P) {
    __shared__ float red[8];
    __shared__ float red2[8];
    int row = blockIdx.x;
    float2* p = (float2*)(P + (size_t)row * MM);
    int tid = threadIdx.x;
    float2 v = p[tid];

    float mx = fmaxf(v.x, v.y);
#pragma unroll
    for (int o = 16; o > 0; o >>= 1) mx = fmaxf(mx, __shfl_xor_sync(0xffffffffu, mx, o));
    if ((tid & 31) == 0) red[tid >> 5] = mx;
    __syncthreads();
    if (tid < 8) {
        float m2 = red[tid];
#pragma unroll
        for (int o = 4; o > 0; o >>= 1) m2 = fmaxf(m2, __shfl_xor_sync(0xffu, m2, o));
        red[tid] = m2;
    }
    __syncthreads();
    mx = red[0];

    float e0 = expf(v.x - mx), e1 = expf(v.y - mx);
    float sm = e0 + e1;
#pragma unroll
    for (int o = 16; o > 0; o >>= 1) sm += __shfl_xor_sync(0xffffffffu, sm, o);
    if ((tid & 31) == 0) red2[tid >> 5] = sm;
    __syncthreads();
    if (tid < 8) {
        float s2 = red2[tid];
#pragma unroll
        for (int o = 4; o > 0; o >>= 1) s2 += __shfl_xor_sync(0xffu, s2, o);
        red2[tid] = s2;
    }
    __syncthreads();
    float inv = 1.0f / red2[0];
    p[tid] = make_float2(e0 * inv + EPSF, e1 * inv + EPSF);
}

// ---------------------------------------------------------------------------
// K4: out[k,m,n] = hard[m,n]*soft[k,m]*x[k,m]; mask[k,m,n] = hard[m,n]*soft[k,m]
// 1 float4 of n per thread; 16 threads per (k,m) row.
// ---------------------------------------------------------------------------
__global__ __launch_bounds__(256) void mask_kernel(const float* __restrict__ x,
                                                   const float* __restrict__ soft,
                                                   const float4* __restrict__ hard4,
                                                   float4* __restrict__ out4,
                                                   float4* __restrict__ mask4) {
    int t = blockIdx.x * 256 + threadIdx.x;   // 0 .. 16,777,215
    int r = t >> 4;                            // (k,m) row
    int n4 = t & 15;
    int m = r & (MM - 1);
    float s  = soft[r];
    float xv = x[r];
    float4 h = hard4[m * 16 + n4];
    float4 mw = make_float4(h.x * s, h.y * s, h.z * s, h.w * s);
    float4 ov = make_float4(mw.x * xv, mw.y * xv, mw.z * xv, mw.w * xv);
    out4[t]  = ov;
    mask4[t] = mw;
}

// ---------------------------------------------------------------------------
extern "C" void kernel_launch(void* const* d_in, const int* in_sizes, int n_in,
                              void* d_out, int out_size) {
    const float* x     = (const float*)d_in[0];
    const float* w_att = (const float*)d_in[1];
    const float* w_b   = (const float*)d_in[2];
    // d_in[3] = l (int32) — compile-time 8, unused

    float* out  = (float*)d_out;
    float* hard = out + HARD_OFF;
    float* soft = out + SOFT_OFF;
    float* mask = out + MASK_OFF;

    hard_kernel<<<1, 512>>>(w_b, hard);

    dim3 gg(KK / 64, MM / 64);
    gemm_kernel<<<gg, 256>>>(x, w_att, soft);

    softmax_kernel<<<KK, 256>>>(soft);

    int total4 = KK * MM * (NN / 4);           // 16,777,216 float4 per array
    mask_kernel<<<total4 / 256, 256>>>(x, soft, (const float4*)hard,
                                       (float4*)out, (float4*)mask);
}

// round 7
// speedup vs baseline: 1.3075x; 1.3075x over previous
#include <cuda_runtime.h>

#define EPSF 1e-8f

#define KK 2048
#define MM 512
#define NN 64

#define HARD_OFF (KK * MM * NN)
#define SOFT_OFF (HARD_OFF + MM * NN)
#define MASK_OFF (SOFT_OFF + KK * MM)

// ---------------------------------------------------------------------------
// K1: per-column 8th-largest threshold of w_b, then scores_hard [M, N]
// ---------------------------------------------------------------------------
__global__ void hard_kernel(const float* __restrict__ w_b, float* __restrict__ hard) {
    __shared__ float thr_s[NN];
    int tid = threadIdx.x;  // 512 threads
    if (tid < NN) {
        float t[8];
#pragma unroll
        for (int j = 0; j < 8; j++) t[j] = -1e30f;
        for (int m = 0; m < MM; m++) {
            float v = w_b[m * NN + tid];
            if (v > t[7]) {
                t[7] = v;
#pragma unroll
                for (int j = 7; j > 0; j--) {
                    if (t[j] > t[j - 1]) { float tmp = t[j]; t[j] = t[j - 1]; t[j - 1] = tmp; }
                }
            }
        }
        thr_s[tid] = t[7];
    }
    __syncthreads();
    for (int idx = tid; idx < MM * NN; idx += 512) {
        int n = idx & (NN - 1);
        float sh = w_b[idx] - thr_s[n] + EPSF;
        float c = fminf(fmaxf(sh, -1.0f), 1.0f);
        hard[idx] = (c + 1.0f) * 0.5f;
    }
}

// ---------------------------------------------------------------------------
// K2: C[2048,512] = A[2048,512] @ B[512,512]
// 128x64 tile, BK=16, 256 threads, 8x4 microtile. Compute-bound tiling.
// ---------------------------------------------------------------------------
__global__ __launch_bounds__(256) void gemm_kernel(const float* __restrict__ A,
                                                   const float* __restrict__ B,
                                                   float* __restrict__ C) {
    __shared__ float As[16][132];   // [k][m], padded
    __shared__ float Bs[16][68];    // [k][n], padded

    int tid  = threadIdx.x;
    int brow = blockIdx.x * 128;
    int bcol = blockIdx.y * 64;
    int tx = tid & 15;        // 0..15 -> 4 cols each
    int ty = tid >> 4;        // 0..15 -> 8 rows each

    float acc[8][4] = {};

    // A load mapping: 128x16 tile = 512 float4, 2 per thread
    int a_m = tid >> 2;            // 0..63
    int a_k = (tid & 3) * 4;       // 0,4,8,12
    // B load mapping: 16x64 tile = 256 float4, 1 per thread
    int b_k = tid >> 4;            // 0..15
    int b_c = (tid & 15) * 4;      // 0..60

    for (int k0 = 0; k0 < MM; k0 += 16) {
#pragma unroll
        for (int j = 0; j < 2; j++) {
            float4 av = *(const float4*)&A[(size_t)(brow + a_m + 64 * j) * MM + k0 + a_k];
            As[a_k + 0][a_m + 64 * j] = av.x;
            As[a_k + 1][a_m + 64 * j] = av.y;
            As[a_k + 2][a_m + 64 * j] = av.z;
            As[a_k + 3][a_m + 64 * j] = av.w;
        }
        float4 bv = *(const float4*)&B[(size_t)(k0 + b_k) * MM + bcol + b_c];
        *(float4*)&Bs[b_k][b_c] = bv;
        __syncthreads();

#pragma unroll
        for (int k = 0; k < 16; k++) {
            float4 a0 = *(const float4*)&As[k][ty * 8];
            float4 a1 = *(const float4*)&As[k][ty * 8 + 4];
            float4 b0 = *(const float4*)&Bs[k][tx * 4];
            float ar[8] = {a0.x, a0.y, a0.z, a0.w, a1.x, a1.y, a1.z, a1.w};
            float br[4] = {b0.x, b0.y, b0.z, b0.w};
#pragma unroll
            for (int i = 0; i < 8; i++)
#pragma unroll
                for (int j = 0; j < 4; j++)
                    acc[i][j] += ar[i] * br[j];
        }
        __syncthreads();
    }

#pragma unroll
    for (int i = 0; i < 8; i++) {
        float4 v = make_float4(acc[i][0], acc[i][1], acc[i][2], acc[i][3]);
        *(float4*)&C[(size_t)(brow + ty * 8 + i) * MM + bcol + tx * 4] = v;
    }
}

// ---------------------------------------------------------------------------
// K3: row softmax over 512 in place, + EPS. One block (256 thr) per row.
// ---------------------------------------------------------------------------
__global__ __launch_bounds__(256) void softmax_kernel(float* __restrict__ P) {
    __shared__ float red[8];
    __shared__ float red2[8];
    int row = blockIdx.x;
    float2* p = (float2*)(P + (size_t)row * MM);
    int tid = threadIdx.x;
    float2 v = p[tid];

    float mx = fmaxf(v.x, v.y);
#pragma unroll
    for (int o = 16; o > 0; o >>= 1) mx = fmaxf(mx, __shfl_xor_sync(0xffffffffu, mx, o));
    if ((tid & 31) == 0) red[tid >> 5] = mx;
    __syncthreads();
    if (tid < 8) {
        float m2 = red[tid];
#pragma unroll
        for (int o = 4; o > 0; o >>= 1) m2 = fmaxf(m2, __shfl_xor_sync(0xffu, m2, o));
        red[tid] = m2;
    }
    __syncthreads();
    mx = red[0];

    float e0 = expf(v.x - mx), e1 = expf(v.y - mx);
    float sm = e0 + e1;
#pragma unroll
    for (int o = 16; o > 0; o >>= 1) sm += __shfl_xor_sync(0xffffffffu, sm, o);
    if ((tid & 31) == 0) red2[tid >> 5] = sm;
    __syncthreads();
    if (tid < 8) {
        float s2 = red2[tid];
#pragma unroll
        for (int o = 4; o > 0; o >>= 1) s2 += __shfl_xor_sync(0xffu, s2, o);
        red2[tid] = s2;
    }
    __syncthreads();
    float inv = 1.0f / red2[0];
    p[tid] = make_float2(e0 * inv + EPSF, e1 * inv + EPSF);
}

// ---------------------------------------------------------------------------
// K4: out[k,m,n] = hard[m,n]*soft[k,m]*x[k,m]; mask[k,m,n] = hard[m,n]*soft[k,m]
// 8 threads per (k,m) row, 2 float4 per thread per array; streaming stores.
// ---------------------------------------------------------------------------
__global__ __launch_bounds__(512) void mask_kernel(const float* __restrict__ x,
                                                   const float* __restrict__ soft,
                                                   const float4* __restrict__ hard4,
                                                   float4* __restrict__ out4,
                                                   float4* __restrict__ mask4) {
    int t = blockIdx.x * 512 + threadIdx.x;   // 0 .. 8,388,607
    int r = t >> 3;                            // (k,m) row
    int j = t & 7;
    int m = r & (MM - 1);
    float s  = __ldg(&soft[r]);
    float xv = __ldg(&x[r]);
    float4 h0 = __ldg(&hard4[m * 16 + j]);
    float4 h1 = __ldg(&hard4[m * 16 + j + 8]);

    float4 mw0 = make_float4(h0.x * s, h0.y * s, h0.z * s, h0.w * s);
    float4 mw1 = make_float4(h1.x * s, h1.y * s, h1.z * s, h1.w * s);
    float4 ov0 = make_float4(mw0.x * xv, mw0.y * xv, mw0.z * xv, mw0.w * xv);
    float4 ov1 = make_float4(mw1.x * xv, mw1.y * xv, mw1.z * xv, mw1.w * xv);

    size_t base = (size_t)r * 16;
    __stcs(&out4[base + j],      ov0);
    __stcs(&out4[base + j + 8],  ov1);
    __stcs(&mask4[base + j],     mw0);
    __stcs(&mask4[base + j + 8], mw1);
}

// ---------------------------------------------------------------------------
extern "C" void kernel_launch(void* const* d_in, const int* in_sizes, int n_in,
                              void* d_out, int out_size) {
    const float* x     = (const float*)d_in[0];
    const float* w_att = (const float*)d_in[1];
    const float* w_b   = (const float*)d_in[2];

    float* out  = (float*)d_out;
    float* hard = out + HARD_OFF;
    float* soft = out + SOFT_OFF;
    float* mask = out + MASK_OFF;

    hard_kernel<<<1, 512>>>(w_b, hard);

    dim3 gg(KK / 128, MM / 64);
    gemm_kernel<<<gg, 256>>>(x, w_att, soft);

    softmax_kernel<<<KK, 256>>>(soft);

    int totalT = KK * MM * 8;                  // 8,388,608 threads
    mask_kernel<<<totalT / 512, 512>>>(x, soft, (const float4*)hard,
                                       (float4*)out, (float4*)mask);
}